// round 11
// baseline (speedup 1.0000x reference)
#include <cuda_runtime.h>
#include <stdint.h>

#define THREADS 512
#define SBINS   2048
#define SSHIFT  21            // key >> 21 -> 2048 sample bins
#define CAP     640
#define FDIM    8192
#define EPT     16
#define VPT     4

// Order-preserving float -> uint32 (ascending)
__device__ __forceinline__ unsigned f2key(float f) {
    unsigned u = __float_as_uint(f);
    return u ^ ((unsigned)((int)u >> 31) | 0x80000000u);
}
// Exact inverse
__device__ __forceinline__ float key2f(unsigned k) {
    unsigned m = (~(unsigned)((int)k >> 31)) | 0x80000000u;
    return __uint_as_float(k ^ m);
}

__global__ __launch_bounds__(THREADS, 3)
void topk_mask_kernel(const float* __restrict__ x, const float* __restrict__ w,
                      const int* __restrict__ kp, float* __restrict__ out)
{
    __shared__ unsigned hist[SBINS];                  // sample histogram, 8 KB
    __shared__ unsigned part[THREADS];                // 2 KB
    __shared__ unsigned listKH[CAP], listIH[CAP], listKL[CAP], listIL[CAP]; // 10 KB
    __shared__ int s_cntH, s_cntL;
    __shared__ unsigned s_EH, s_EL;                   // loose edge keys
    __shared__ unsigned s_Th, s_Ih, s_Tl, s_Il;
    __shared__ int s_red;
    __shared__ int s_K;

    const int tid  = threadIdx.x;
    const int lane = tid & 31;
    const int warp = tid >> 5;
    const int b    = blockIdx.x;

    if (tid == 0) {
        s_cntH = 0; s_cntL = 0;
        s_EH = 0u; s_EL = 0xFFFFFFFFu;   // safe defaults -> overflow -> fallback
        s_K = kp ? kp[0] : 64;
    }
    ((uint4*)hist)[tid] = make_uint4(0,0,0,0);   // 2048 words = 512 * uint4
    __syncthreads();
    const int K = s_K;
    int sr = (2 * K * 1024) / FDIM + 12;         // sample rank target w/ margin
    if (sr > 1024) sr = 1024;
    if (sr < 1)    sr = 1;
    const int SRANK = sr;

    const float4* xr = (const float4*)(x + (size_t)b * FDIM);
    const float4* wr = (const float4*)w;
    float4* orow     = (float4*)(out + (size_t)b * FDIM);

    // ---- P0: load, multiply, keys (registers); 2 sample atomics/thread ----
    unsigned key[EPT];
    #pragma unroll
    for (int k = 0; k < VPT; k++) {
        int v = tid + k * THREADS;
        float4 xv = xr[v];
        float4 wv = wr[v];
        key[4*k+0] = f2key(xv.x * wv.x);
        key[4*k+1] = f2key(xv.y * wv.y);
        key[4*k+2] = f2key(xv.z * wv.z);
        key[4*k+3] = f2key(xv.w * wv.w);
    }
    atomicAdd(&hist[key[0] >> SSHIFT], 1u);
    atomicAdd(&hist[key[8] >> SSHIFT], 1u);
    __syncthreads();

    // ---- P1a: partial sums, 4 bins per thread ----
    {
        uint4 a = ((const uint4*)hist)[tid];
        part[tid] = a.x + a.y + a.z + a.w;
    }
    __syncthreads();

    // ---- P1b: sample resolve -> loose edges. warp0 = top, warp1 = bottom ----
    if (warp == 0) {
        unsigned g = 0;
        #pragma unroll
        for (int p = 0; p < 16; p++) g += part[lane*16 + p];
        unsigned acc = g;
        #pragma unroll
        for (int off = 1; off < 32; off <<= 1) {
            unsigned vv = __shfl_down_sync(0xFFFFFFFFu, acc, off);
            if (lane + off < 32) acc += vv;
        }
        unsigned above = acc - g;
        if ((int)above < SRANK && (int)(above + g) >= SRANK) {
            unsigned run = above;
            int base = lane * 16;
            for (int p = 15; p >= 0; --p) {
                unsigned pc = part[base + p];
                if ((int)(run + pc) >= SRANK) {
                    int bb = (base + p) * 4;
                    for (int b4 = 3; b4 >= 0; --b4) {
                        unsigned c = hist[bb + b4];
                        if ((int)(run + c) >= SRANK) {
                            s_EH = (unsigned)(bb + b4) << SSHIFT;   // bin lower edge
                            break;
                        }
                        run += c;
                    }
                    break;
                }
                run += pc;
            }
        }
    } else if (warp == 1) {
        unsigned g = 0;
        #pragma unroll
        for (int p = 0; p < 16; p++) g += part[lane*16 + p];
        unsigned acc = g;
        #pragma unroll
        for (int off = 1; off < 32; off <<= 1) {
            unsigned vv = __shfl_up_sync(0xFFFFFFFFu, acc, off);
            if (lane >= off) acc += vv;
        }
        unsigned below = acc - g;
        if ((int)below < SRANK && (int)(below + g) >= SRANK) {
            unsigned run = below;
            int base = lane * 16;
            for (int p = 0; p < 16; ++p) {
                unsigned pc = part[base + p];
                if ((int)(run + pc) >= SRANK) {
                    int bb = (base + p) * 4;
                    for (int b4 = 0; b4 < 4; ++b4) {
                        unsigned c = hist[bb + b4];
                        if ((int)(run + c) >= SRANK) {
                            s_EL = ((unsigned)(bb + b4) << SSHIFT) | ((1u << SSHIFT) - 1u); // upper edge
                            break;
                        }
                        run += c;
                    }
                    break;
                }
                run += pc;
            }
        }
    }
    __syncthreads();

    // ---- P2: gather candidates beyond loose edges (counter = exact count) ----
    {
        const unsigned EH = s_EH, EL = s_EL;
        #pragma unroll
        for (int e = 0; e < EPT; e++) {
            unsigned kk  = key[e];
            unsigned idx = (unsigned)(tid*4 + (e>>2)*2048 + (e&3));
            if (kk >= EH) {
                int p = atomicAdd(&s_cntH, 1);
                if (p < CAP) { listKH[p] = kk; listIH[p] = idx; }
            }
            if (kk <= EL) {
                int p = atomicAdd(&s_cntL, 1);
                if (p < CAP) { listKL[p] = kk; listIL[p] = idx; }
            }
        }
    }
    __syncthreads();

    const int nH = s_cntH, nL = s_cntL;
    const bool fbH = (nH < K) || (nH > CAP);
    const bool fbL = (nL < K) || (nL > CAP);

    // ---- P3: exact in-list rank (strided: covers ALL list positions <= CAP) ----
    if (!fbH) {
        for (int j = tid; j < nH; j += THREADS) {
            unsigned kj = listKH[j], ij = listIH[j];
            int rank = 0;
            for (int i = 0; i < nH; i++) {
                unsigned ki = listKH[i], ii = listIH[i];
                rank += (ki > kj) || (ki == kj && ii < ij);
            }
            if (rank == K - 1) { s_Th = kj; s_Ih = ij; }
        }
    }
    if (!fbL) {
        for (int j = tid; j < nL; j += THREADS) {
            unsigned kj = listKL[j], ij = listIL[j];
            int rank = 0;
            for (int i = 0; i < nL; i++) {
                unsigned ki = listKL[i], ii = listIL[i];
                rank += (ki < kj) || (ki == kj && ii < ij);
            }
            if (rank == K - 1) { s_Tl = kj; s_Il = ij; }
        }
    }

    // ---- Rare exact fallback: block-uniform binary search on keys, then index ----
    if (fbH) {
        unsigned lo = 0, hi = 0xFFFFFFFFu;
        for (int it = 0; it < 32; ++it) {
            unsigned mid = lo + ((hi - lo) >> 1);
            if (tid == 0) s_red = 0;
            __syncthreads();
            int c = 0;
            #pragma unroll
            for (int e = 0; e < EPT; e++) c += (key[e] > mid);
            c = __reduce_add_sync(0xFFFFFFFFu, c);
            if (lane == 0) atomicAdd(&s_red, c);
            __syncthreads();
            int tot = s_red; __syncthreads();
            if (tot >= K) lo = mid + 1; else hi = mid;
        }
        unsigned Th = lo;
        if (tid == 0) s_red = 0;
        __syncthreads();
        { int c = 0;
          #pragma unroll
          for (int e = 0; e < EPT; e++) c += (key[e] > Th);
          c = __reduce_add_sync(0xFFFFFFFFu, c);
          if (lane == 0) atomicAdd(&s_red, c); }
        __syncthreads();
        int r = K - s_red; __syncthreads();
        unsigned lo2 = 0, hi2 = FDIM - 1;
        for (int it = 0; it < 13; ++it) {
            unsigned mid = lo2 + ((hi2 - lo2) >> 1);
            if (tid == 0) s_red = 0;
            __syncthreads();
            int c = 0;
            #pragma unroll
            for (int e = 0; e < EPT; e++) {
                unsigned idx = (unsigned)(tid*4 + (e>>2)*2048 + (e&3));
                c += (key[e] == Th && idx <= mid);
            }
            c = __reduce_add_sync(0xFFFFFFFFu, c);
            if (lane == 0) atomicAdd(&s_red, c);
            __syncthreads();
            int tot = s_red; __syncthreads();
            if (tot >= r) hi2 = mid; else lo2 = mid + 1;
        }
        if (tid == 0) { s_Th = Th; s_Ih = lo2; }
    }
    if (fbL) {
        unsigned lo = 0, hi = 0xFFFFFFFFu;
        for (int it = 0; it < 32; ++it) {
            unsigned mid = lo + ((hi - lo) >> 1);
            if (tid == 0) s_red = 0;
            __syncthreads();
            int c = 0;
            #pragma unroll
            for (int e = 0; e < EPT; e++) c += (key[e] <= mid);
            c = __reduce_add_sync(0xFFFFFFFFu, c);
            if (lane == 0) atomicAdd(&s_red, c);
            __syncthreads();
            int tot = s_red; __syncthreads();
            if (tot >= K) hi = mid; else lo = mid + 1;
        }
        unsigned Tl = lo;
        if (tid == 0) s_red = 0;
        __syncthreads();
        { int c = 0;
          #pragma unroll
          for (int e = 0; e < EPT; e++) c += (key[e] < Tl);
          c = __reduce_add_sync(0xFFFFFFFFu, c);
          if (lane == 0) atomicAdd(&s_red, c); }
        __syncthreads();
        int r = K - s_red; __syncthreads();
        unsigned lo2 = 0, hi2 = FDIM - 1;
        for (int it = 0; it < 13; ++it) {
            unsigned mid = lo2 + ((hi2 - lo2) >> 1);
            if (tid == 0) s_red = 0;
            __syncthreads();
            int c = 0;
            #pragma unroll
            for (int e = 0; e < EPT; e++) {
                unsigned idx = (unsigned)(tid*4 + (e>>2)*2048 + (e&3));
                c += (key[e] == Tl && idx <= mid);
            }
            c = __reduce_add_sync(0xFFFFFFFFu, c);
            if (lane == 0) atomicAdd(&s_red, c);
            __syncthreads();
            int tot = s_red; __syncthreads();
            if (tot >= r) hi2 = mid; else lo2 = mid + 1;
        }
        if (tid == 0) { s_Tl = Tl; s_Il = lo2; }
    }
    __syncthreads();

    // ---- P4: masked write-out ----
    const unsigned Th = s_Th, Ih = s_Ih, Tl = s_Tl, Il = s_Il;
    #pragma unroll
    for (int k = 0; k < VPT; k++) {
        float vals[4];
        #pragma unroll
        for (int c = 0; c < 4; c++) {
            unsigned kk  = key[4*k + c];
            unsigned idx = (unsigned)(tid*4 + k*2048 + c);
            bool z = (kk > Th) || (kk < Tl) ||
                     (kk == Th && idx <= Ih) ||
                     (kk == Tl && idx <= Il);
            vals[c] = z ? 0.0f : key2f(kk);
        }
        float4 o; o.x = vals[0]; o.y = vals[1]; o.z = vals[2]; o.w = vals[3];
        orow[tid + k * THREADS] = o;
    }
}

extern "C" void kernel_launch(void* const* d_in, const int* in_sizes, int n_in,
                              void* d_out, int out_size)
{
    const float* x = (const float*)d_in[0];
    const float* w = (const float*)d_in[1];
    const int* kp  = (n_in >= 3) ? (const int*)d_in[2] : nullptr;

    int Fdim = in_sizes[1];
    int B    = in_sizes[0] / Fdim;

    topk_mask_kernel<<<B, THREADS>>>(x, w, kp, (float*)d_out);
}